// round 1
// baseline (speedup 1.0000x reference)
#include <cuda_runtime.h>
#include <math.h>

#define Nn 50000
#define Dd 256
#define Hh 64
#define Ee 1600000
#define NLO 40000
#define NHI 10000
#define ROWS (2*Nn)

// Scratch (static device allocations are the sanctioned workaround)
__device__ float g_filt[(size_t)ROWS*Dd];   // [2N,256]: rows [0,N)=lowpass, [N,2N)=highpass
__device__ float g_s[ROWS*2];               // per filtered row: {mlp_src, mlp_dst}
__device__ float g_wsrc[Nn];
__device__ float g_wdst[Nn];
__device__ double g_part[2048];

// ---------------------------------------------------------------------------
// K1: IIR (direct form II transposed) along features, one thread per chain.
// ---------------------------------------------------------------------------
__global__ void __launch_bounds__(256) k_iir(const float* __restrict__ x,
    const float* __restrict__ bhi, const float* __restrict__ ahi,
    const float* __restrict__ blo, const float* __restrict__ alo)
{
    int t = blockIdx.x * 256 + threadIdx.x;      // chain id == g_filt row
    if (t >= ROWS) return;
    int f = (t >= Nn);
    int n = t - f * Nn;
    const float* bc = f ? bhi : ahi - 6;         // placeholder avoided below
    bc = f ? bhi : blo;
    const float* ac = f ? ahi : alo;
    float inv = 1.0f / ac[0];
    float b0 = bc[0]*inv, b1 = bc[1]*inv, b2 = bc[2]*inv,
          b3 = bc[3]*inv, b4 = bc[4]*inv, b5 = bc[5]*inv;
    float a1 = ac[1]*inv, a2 = ac[2]*inv, a3 = ac[3]*inv,
          a4 = ac[4]*inv, a5 = ac[5]*inv;
    float z0=0.f, z1=0.f, z2=0.f, z3=0.f, z4=0.f;
    const float* xr = x + (size_t)n * Dd;
    float* yr = g_filt + (size_t)t * Dd;
    for (int d0 = 0; d0 < Dd; d0 += 8) {
        float yb[8];
#pragma unroll
        for (int q = 0; q < 8; q++) {
            float xv = __ldg(xr + d0 + q);
            float y  = fmaf(b0, xv, z0);
            z0 = fmaf(-a1, y, fmaf(b1, xv, z1));
            z1 = fmaf(-a2, y, fmaf(b2, xv, z2));
            z2 = fmaf(-a3, y, fmaf(b3, xv, z3));
            z3 = fmaf(-a4, y, fmaf(b4, xv, z4));
            z4 = fmaf(-a5, y, b5 * xv);
            yb[q] = y;
        }
        *(float4*)(yr + d0)     = make_float4(yb[0], yb[1], yb[2], yb[3]);
        *(float4*)(yr + d0 + 4) = make_float4(yb[4], yb[5], yb[6], yb[7]);
    }
}

// ---------------------------------------------------------------------------
// K2: fused GEMM [2N,256]@[256,128] + bias + ReLU + w2-dot epilogue.
// Packed f32x2 FMA (FFMA2) for 2x fp32 rate. Tile 128 rows x 128 cols.
// Thread (i=t/16, j=t%16): rows 8i..8i+7, col pairs (2j+32m, 2j+1+32m), m=0..3.
// m<2 -> src half (cols<64), m>=2 -> dst half.
// ---------------------------------------------------------------------------
__device__ __forceinline__ unsigned long long pk2(float x, float y) {
    unsigned long long r;
    asm("mov.b64 %0, {%1, %2};" : "=l"(r) : "f"(x), "f"(y));
    return r;
}
__device__ __forceinline__ void upk2(unsigned long long v, float& x, float& y) {
    asm("mov.b64 {%0, %1}, %2;" : "=f"(x), "=f"(y) : "l"(v));
}
__device__ __forceinline__ unsigned long long ffma2(unsigned long long a,
                                                    unsigned long long b,
                                                    unsigned long long c) {
    unsigned long long d;
    asm("fma.rn.f32x2 %0, %1, %2, %3;" : "=l"(d) : "l"(a), "l"(b), "l"(c));
    return d;
}

#define KCH 32      // k-chunk
#define AS_LD 36    // padded lane stride for A tile

__global__ void __launch_bounds__(256) k_gemm(
    const float* __restrict__ w1s, const float* __restrict__ w1d,
    const float* __restrict__ b1s, const float* __restrict__ b1d,
    const float* __restrict__ w2s, const float* __restrict__ w2d,
    const float* __restrict__ b2s, const float* __restrict__ b2d)
{
    __shared__ float Ws[KCH * 128];      // 16 KB
    __shared__ float As[128 * AS_LD];    // 18 KB

    int t = threadIdx.x;
    int i = t >> 4, j = t & 15;
    int r0 = blockIdx.x * 128;

    // per-thread bias/w2 pairs for its 8 columns
    float2 b1v[4], w2v[4];
#pragma unroll
    for (int m = 0; m < 4; m++) {
        int c = 2*j + 32*m;
        if (c < 64) {
            b1v[m] = make_float2(__ldg(b1s + c), __ldg(b1s + c + 1));
            w2v[m] = make_float2(__ldg(w2s + c), __ldg(w2s + c + 1));
        } else {
            b1v[m] = make_float2(__ldg(b1d + c - 64), __ldg(b1d + c - 63));
            w2v[m] = make_float2(__ldg(w2d + c - 64), __ldg(w2d + c - 63));
        }
    }
    float b2v0 = __ldg(b2s), b2v1 = __ldg(b2d);

    unsigned long long acc[8][4];
#pragma unroll
    for (int r = 0; r < 8; r++)
#pragma unroll
        for (int m = 0; m < 4; m++) acc[r][m] = 0ull;

    for (int kc = 0; kc < 256; kc += KCH) {
        __syncthreads();
        // stage W chunk [KCH][128] (concat src|dst)
        for (int idx = t; idx < KCH * 32; idx += 256) {
            int kk = idx >> 5;
            int c  = (idx & 31) * 4;
            int k  = kc + kk;
            float4 v;
            if (c < 64) v = *(const float4*)(w1s + k * 64 + c);
            else        v = *(const float4*)(w1d + k * 64 + (c - 64));
            *(float4*)&Ws[kk * 128 + c] = v;
        }
        // stage A chunk [128][KCH]
        for (int idx = t; idx < 128 * 8; idx += 256) {
            int r  = idx >> 3;
            int kq = (idx & 7) * 4;
            int gr = r0 + r;
            float4 v = make_float4(0.f, 0.f, 0.f, 0.f);
            if (gr < ROWS) v = *(const float4*)&g_filt[(size_t)gr * Dd + kc + kq];
            *(float4*)&As[r * AS_LD + kq] = v;
        }
        __syncthreads();

#pragma unroll
        for (int kk = 0; kk < KCH; kk += 4) {
            float4 av[8];
#pragma unroll
            for (int r = 0; r < 8; r++)
                av[r] = *(const float4*)&As[(8*i + r) * AS_LD + kk];
#pragma unroll
            for (int q = 0; q < 4; q++) {
                unsigned long long bb[4];
                const float* wrow = &Ws[(kk + q) * 128];
#pragma unroll
                for (int m = 0; m < 4; m++)
                    bb[m] = *(const unsigned long long*)&wrow[2*j + 32*m];
#pragma unroll
                for (int r = 0; r < 8; r++) {
                    float a = (q == 0) ? av[r].x : (q == 1) ? av[r].y
                            : (q == 2) ? av[r].z : av[r].w;
                    unsigned long long a2 = pk2(a, a);
#pragma unroll
                    for (int m = 0; m < 4; m++)
                        acc[r][m] = ffma2(a2, bb[m], acc[r][m]);
                }
            }
        }
    }

    // epilogue: relu(acc + b1) . w2, reduce over the 16 j-lanes per (row, half)
    float p[8][2];
#pragma unroll
    for (int r = 0; r < 8; r++) {
        p[r][0] = 0.f; p[r][1] = 0.f;
#pragma unroll
        for (int m = 0; m < 4; m++) {
            float v0, v1;
            upk2(acc[r][m], v0, v1);
            int h = m >> 1;
            p[r][h] += fmaxf(v0 + b1v[m].x, 0.f) * w2v[m].x
                     + fmaxf(v1 + b1v[m].y, 0.f) * w2v[m].y;
        }
    }
#pragma unroll
    for (int off = 8; off; off >>= 1) {
#pragma unroll
        for (int r = 0; r < 8; r++) {
            p[r][0] += __shfl_xor_sync(0xffffffffu, p[r][0], off);
            p[r][1] += __shfl_xor_sync(0xffffffffu, p[r][1], off);
        }
    }
    if (j == 0) {
#pragma unroll
        for (int r = 0; r < 8; r++) {
            int gr = r0 + 8*i + r;
            if (gr < ROWS) {
                g_s[gr*2 + 0] = p[r][0] + b2v0;
                g_s[gr*2 + 1] = p[r][1] + b2v1;
            }
        }
    }
}

// ---------------------------------------------------------------------------
// K3: subsample/concat gather -> w_src[N], w_dst[N]
// ---------------------------------------------------------------------------
__global__ void __launch_bounds__(256) k_gather(
    const int* __restrict__ ish, const int* __restrict__ isl,
    const int* __restrict__ idh, const int* __restrict__ idl)
{
    int i = blockIdx.x * 256 + threadIdx.x;
    if (i >= Nn) return;
    int rs, rd;
    if (i < NLO) { rs = __ldg(isl + i);            rd = __ldg(idl + i); }
    else         { rs = Nn + __ldg(ish + i - NLO); rd = Nn + __ldg(idh + i - NLO); }
    g_wsrc[i] = g_s[rs*2 + 0];
    g_wdst[i] = g_s[rd*2 + 1];
}

// ---------------------------------------------------------------------------
// K4: edge gate + per-block deterministic partial sums
// ---------------------------------------------------------------------------
__global__ void __launch_bounds__(256) k_edge(
    const int* __restrict__ src, const int* __restrict__ dst,
    const float* __restrict__ u, float* __restrict__ out)
{
    __shared__ double red[256];
    int t = threadIdx.x;
    int base = (blockIdx.x * 256 + t) * 4;
    double local = 0.0;
    if (base < Ee) {  // Ee % 4 == 0, so full quads
        int4   s4 = *(const int4*)(src + base);
        int4   d4 = *(const int4*)(dst + base);
        float4 u4 = *(const float4*)(u + base);
        float w[4] = { g_wsrc[s4.x] + g_wdst[d4.x],
                       g_wsrc[s4.y] + g_wdst[d4.y],
                       g_wsrc[s4.z] + g_wdst[d4.z],
                       g_wsrc[s4.w] + g_wdst[d4.w] };
        float uu[4] = { u4.x, u4.y, u4.z, u4.w };
#pragma unroll
        for (int q = 0; q < 4; q++) {
            float eps = 0.9999f - 0.9998f * uu[q];
            float g   = (logf(eps) - log1pf(-eps) + w[q]) * 2.0f;  // /0.5
            float aug = 1.0f / (1.0f + expf(-g));
            out[1 + base + q] = aug;
            local += (double)aug;
        }
    }
    red[t] = local;
    __syncthreads();
    for (int off = 128; off; off >>= 1) {
        if (t < off) red[t] += red[t + off];
        __syncthreads();
    }
    if (t == 0) g_part[blockIdx.x] = red[0];
}

#define NPART 1563
__global__ void __launch_bounds__(256) k_final(float* __restrict__ out)
{
    __shared__ double red[256];
    int t = threadIdx.x;
    double local = 0.0;
    for (int idx = t; idx < NPART; idx += 256) local += g_part[idx];
    red[t] = local;
    __syncthreads();
    for (int off = 128; off; off >>= 1) {
        if (t < off) red[t] += red[t + off];
        __syncthreads();
    }
    if (t == 0) out[0] = (float)(1.0 - red[0] / (double)Ee);
}

// ---------------------------------------------------------------------------
extern "C" void kernel_launch(void* const* d_in, const int* in_sizes, int n_in,
                              void* d_out, int out_size)
{
    const float* node_emb = (const float*)d_in[0];
    const float* w1_src   = (const float*)d_in[1];
    const float* b1_src   = (const float*)d_in[2];
    const float* w2_src   = (const float*)d_in[3];
    const float* b2_src   = (const float*)d_in[4];
    const float* w1_dst   = (const float*)d_in[5];
    const float* b1_dst   = (const float*)d_in[6];
    const float* w2_dst   = (const float*)d_in[7];
    const float* b2_dst   = (const float*)d_in[8];
    const float* b_hi     = (const float*)d_in[9];
    const float* a_hi     = (const float*)d_in[10];
    const float* b_lo     = (const float*)d_in[11];
    const float* a_lo     = (const float*)d_in[12];
    const float* u_eps    = (const float*)d_in[13];
    const int*   src      = (const int*)d_in[14];
    const int*   dst      = (const int*)d_in[15];
    const int*   idx_src_hi = (const int*)d_in[16];
    const int*   idx_src_lo = (const int*)d_in[17];
    const int*   idx_dst_hi = (const int*)d_in[18];
    const int*   idx_dst_lo = (const int*)d_in[19];
    float* out = (float*)d_out;

    k_iir<<<(ROWS + 255) / 256, 256>>>(node_emb, b_hi, a_hi, b_lo, a_lo);
    k_gemm<<<(ROWS + 127) / 128, 256>>>(w1_src, w1_dst, b1_src, b1_dst,
                                        w2_src, w2_dst, b2_src, b2_dst);
    k_gather<<<(Nn + 255) / 256, 256>>>(idx_src_hi, idx_src_lo,
                                        idx_dst_hi, idx_dst_lo);
    k_edge<<<NPART, 256>>>(src, dst, u_eps, out);
    k_final<<<1, 256>>>(out);
}

// round 2
// speedup vs baseline: 1.6849x; 1.6849x over previous
#include <cuda_runtime.h>
#include <math.h>

#define Nn 50000
#define Ee 1600000
#define NLO 40000
#define ROWS (2*Nn)

// Scratch (static device arrays are the sanctioned workaround)
__device__ float g_s[ROWS*2];     // per filtered row: {mlp_src, mlp_dst}
__device__ float g_wsrc[Nn];
__device__ float g_wdst[Nn];
__device__ double g_part[2048];

// ---- packed f32x2 helpers ------------------------------------------------
__device__ __forceinline__ unsigned long long pk2(float x, float y) {
    unsigned long long r;
    asm("mov.b64 %0, {%1, %2};" : "=l"(r) : "f"(x), "f"(y));
    return r;
}
__device__ __forceinline__ void upk2(unsigned long long v, float& x, float& y) {
    asm("mov.b64 {%0, %1}, %2;" : "=f"(x), "=f"(y) : "l"(v));
}
__device__ __forceinline__ unsigned long long ffma2(unsigned long long a,
                                                    unsigned long long b,
                                                    unsigned long long c) {
    unsigned long long d;
    asm("fma.rn.f32x2 %0, %1, %2, %3;" : "=l"(d) : "l"(a), "l"(b), "l"(c));
    return d;
}

// ---------------------------------------------------------------------------
// Fused kernel: IIR along features (one thread per filtered row) + both MLP
// hidden layers accumulated on the fly (128 hidden cols as 64 f32x2 regs),
// + ReLU + w2-dot epilogue. Input and W1 tiles staged coalesced via smem.
// blockIdx.y: 0 = lowpass rows [0,N), 1 = highpass rows [N,2N).
// ---------------------------------------------------------------------------
__global__ void __launch_bounds__(128, 2) k_fused(
    const float* __restrict__ x,
    const float* __restrict__ w1s, const float* __restrict__ w1d,
    const float* __restrict__ b1s, const float* __restrict__ b1d,
    const float* __restrict__ w2s, const float* __restrict__ w2d,
    const float* __restrict__ b2s, const float* __restrict__ b2d,
    const float* __restrict__ bhi, const float* __restrict__ ahi,
    const float* __restrict__ blo, const float* __restrict__ alo)
{
    __shared__ float Xs[128*33];                               // input tile, padded
    __shared__ __align__(16) unsigned long long Wsm[32*64];    // W1 tile as f32 pairs
    __shared__ float b1c[128], w2c[128];

    int t  = threadIdx.x;
    int f  = blockIdx.y;
    int n0 = blockIdx.x * 128;
    int n  = n0 + t;

    b1c[t] = (t < 64) ? __ldg(b1s + t) : __ldg(b1d + t - 64);
    w2c[t] = (t < 64) ? __ldg(w2s + t) : __ldg(w2d + t - 64);

    const float* bc = f ? bhi : blo;
    const float* ac = f ? ahi : alo;
    float inv = 1.0f / __ldg(ac);
    float cb0 = __ldg(bc+0)*inv, cb1 = __ldg(bc+1)*inv, cb2 = __ldg(bc+2)*inv,
          cb3 = __ldg(bc+3)*inv, cb4 = __ldg(bc+4)*inv, cb5 = __ldg(bc+5)*inv;
    float ca1 = __ldg(ac+1)*inv, ca2 = __ldg(ac+2)*inv, ca3 = __ldg(ac+3)*inv,
          ca4 = __ldg(ac+4)*inv, ca5 = __ldg(ac+5)*inv;

    unsigned long long acc[64];
#pragma unroll
    for (int c = 0; c < 64; c++) acc[c] = 0ull;
    float z0 = 0.f, z1 = 0.f, z2 = 0.f, z3 = 0.f, z4 = 0.f;

    for (int d0 = 0; d0 < 256; d0 += 32) {
        __syncthreads();
        // stage W1 tile [32 k][128 cols] (src cols 0-63 | dst cols 64-127)
        for (int idx = t; idx < 1024; idx += 128) {
            int kk = idx >> 5, c4 = (idx & 31) << 2;
            const float* wp = (c4 < 64) ? (w1s + (d0 + kk)*64 + c4)
                                        : (w1d + (d0 + kk)*64 + (c4 - 64));
            float4 v = *(const float4*)wp;
            *(float4*)((float*)Wsm + kk*128 + c4) = v;
        }
        // stage X tile [128 rows][32 cols], coalesced
        for (int idx = t; idx < 1024; idx += 128) {
            int row = idx >> 3, c4 = (idx & 7) << 2;
            int gr = n0 + row;
            float4 v = make_float4(0.f, 0.f, 0.f, 0.f);
            if (gr < Nn) v = *(const float4*)(x + (size_t)gr*256 + d0 + c4);
            float* dp = &Xs[row*33 + c4];
            dp[0] = v.x; dp[1] = v.y; dp[2] = v.z; dp[3] = v.w;
        }
        __syncthreads();

#pragma unroll 4
        for (int dd = 0; dd < 32; dd++) {
            float xv = Xs[t*33 + dd];
            float y  = fmaf(cb0, xv, z0);
            z0 = fmaf(-ca1, y, fmaf(cb1, xv, z1));
            z1 = fmaf(-ca2, y, fmaf(cb2, xv, z2));
            z2 = fmaf(-ca3, y, fmaf(cb3, xv, z3));
            z3 = fmaf(-ca4, y, fmaf(cb4, xv, z4));
            z4 = fmaf(-ca5, y, cb5 * xv);
            unsigned long long y2 = pk2(y, y);
            const ulonglong2* wr = (const ulonglong2*)(Wsm + dd*64);
#pragma unroll
            for (int c2 = 0; c2 < 32; c2++) {
                ulonglong2 wv = wr[c2];
                acc[2*c2]   = ffma2(y2, wv.x, acc[2*c2]);
                acc[2*c2+1] = ffma2(y2, wv.y, acc[2*c2+1]);
            }
        }
    }

    // epilogue: relu(h + b1) . w2 for src half (cols 0-63) and dst half (64-127)
    float ps = 0.f, pd = 0.f;
#pragma unroll
    for (int c = 0; c < 32; c++) {
        float v0, v1; upk2(acc[c], v0, v1);
        ps += fmaxf(v0 + b1c[2*c], 0.f)   * w2c[2*c]
            + fmaxf(v1 + b1c[2*c+1], 0.f) * w2c[2*c+1];
    }
#pragma unroll
    for (int c = 32; c < 64; c++) {
        float v0, v1; upk2(acc[c], v0, v1);
        pd += fmaxf(v0 + b1c[2*c], 0.f)   * w2c[2*c]
            + fmaxf(v1 + b1c[2*c+1], 0.f) * w2c[2*c+1];
    }
    if (n < Nn) {
        int gr = f * Nn + n;
        g_s[gr*2 + 0] = ps + __ldg(b2s);
        g_s[gr*2 + 1] = pd + __ldg(b2d);
    }
}

// ---------------------------------------------------------------------------
// K3: subsample/concat gather -> w_src[N], w_dst[N]
// ---------------------------------------------------------------------------
__global__ void __launch_bounds__(256) k_gather(
    const int* __restrict__ ish, const int* __restrict__ isl,
    const int* __restrict__ idh, const int* __restrict__ idl)
{
    int i = blockIdx.x * 256 + threadIdx.x;
    if (i >= Nn) return;
    int rs, rd;
    if (i < NLO) { rs = __ldg(isl + i);            rd = __ldg(idl + i); }
    else         { rs = Nn + __ldg(ish + i - NLO); rd = Nn + __ldg(idh + i - NLO); }
    g_wsrc[i] = g_s[rs*2 + 0];
    g_wdst[i] = g_s[rd*2 + 1];
}

// ---------------------------------------------------------------------------
// K4: edge gate (log-free sigmoid identity) + per-block partial sums
// sigmoid((logit(eps)+w)/0.5) = 1 / (1 + ((1-eps)/eps)^2 * exp(-2w))
// ---------------------------------------------------------------------------
__global__ void __launch_bounds__(256) k_edge(
    const int* __restrict__ src, const int* __restrict__ dst,
    const float* __restrict__ u, float* __restrict__ out)
{
    __shared__ double red[256];
    int t = threadIdx.x;
    int base = (blockIdx.x * 256 + t) * 4;
    double local = 0.0;
    if (base < Ee) {  // Ee % 4 == 0
        int4   s4 = *(const int4*)(src + base);
        int4   d4 = *(const int4*)(dst + base);
        float4 u4 = *(const float4*)(u + base);
        float w[4] = { __ldg(&g_wsrc[s4.x]) + __ldg(&g_wdst[d4.x]),
                       __ldg(&g_wsrc[s4.y]) + __ldg(&g_wdst[d4.y]),
                       __ldg(&g_wsrc[s4.z]) + __ldg(&g_wdst[d4.z]),
                       __ldg(&g_wsrc[s4.w]) + __ldg(&g_wdst[d4.w]) };
        float uu[4] = { u4.x, u4.y, u4.z, u4.w };
#pragma unroll
        for (int q = 0; q < 4; q++) {
            float eps   = 0.9999f - 0.9998f * uu[q];
            float onem  = 0.0001f + 0.9998f * uu[q];      // 1 - eps
            float r     = __fdividef(onem, eps);
            float gexp  = __expf(-2.0f * w[q]);
            float aug   = __fdividef(1.0f, fmaf(r * r, gexp, 1.0f));
            out[1 + base + q] = aug;
            local += (double)aug;
        }
    }
    red[t] = local;
    __syncthreads();
    for (int off = 128; off; off >>= 1) {
        if (t < off) red[t] += red[t + off];
        __syncthreads();
    }
    if (t == 0) g_part[blockIdx.x] = red[0];
}

#define NPART 1563
__global__ void __launch_bounds__(256) k_final(float* __restrict__ out)
{
    __shared__ double red[256];
    int t = threadIdx.x;
    double local = 0.0;
    for (int idx = t; idx < NPART; idx += 256) local += g_part[idx];
    red[t] = local;
    __syncthreads();
    for (int off = 128; off; off >>= 1) {
        if (t < off) red[t] += red[t + off];
        __syncthreads();
    }
    if (t == 0) out[0] = (float)(1.0 - red[0] / (double)Ee);
}

// ---------------------------------------------------------------------------
extern "C" void kernel_launch(void* const* d_in, const int* in_sizes, int n_in,
                              void* d_out, int out_size)
{
    const float* node_emb = (const float*)d_in[0];
    const float* w1_src   = (const float*)d_in[1];
    const float* b1_src   = (const float*)d_in[2];
    const float* w2_src   = (const float*)d_in[3];
    const float* b2_src   = (const float*)d_in[4];
    const float* w1_dst   = (const float*)d_in[5];
    const float* b1_dst   = (const float*)d_in[6];
    const float* w2_dst   = (const float*)d_in[7];
    const float* b2_dst   = (const float*)d_in[8];
    const float* b_hi     = (const float*)d_in[9];
    const float* a_hi     = (const float*)d_in[10];
    const float* b_lo     = (const float*)d_in[11];
    const float* a_lo     = (const float*)d_in[12];
    const float* u_eps    = (const float*)d_in[13];
    const int*   src      = (const int*)d_in[14];
    const int*   dst      = (const int*)d_in[15];
    const int*   idx_src_hi = (const int*)d_in[16];
    const int*   idx_src_lo = (const int*)d_in[17];
    const int*   idx_dst_hi = (const int*)d_in[18];
    const int*   idx_dst_lo = (const int*)d_in[19];
    float* out = (float*)d_out;

    dim3 gf((Nn + 127) / 128, 2);
    k_fused<<<gf, 128>>>(node_emb, w1_src, w1_dst, b1_src, b1_dst,
                         w2_src, w2_dst, b2_src, b2_dst,
                         b_hi, a_hi, b_lo, a_lo);
    k_gather<<<(Nn + 255) / 256, 256>>>(idx_src_hi, idx_src_lo,
                                        idx_dst_hi, idx_dst_lo);
    k_edge<<<NPART, 256>>>(src, dst, u_eps, out);
    k_final<<<1, 256>>>(out);
}

// round 3
// speedup vs baseline: 2.2772x; 1.3515x over previous
#include <cuda_runtime.h>
#include <math.h>

#define Nn 50000
#define Ee 1600000
#define NLO 40000
#define NHI 10000

// Scratch
__device__ float g_h[2][256];            // impulse responses: [0]=lo, [1]=hi
__device__ float g_wt[4 * 256 * 64];     // folded W1: combo = br*2+f, [k][c]
__device__ float g_wsrc[Nn];
__device__ float g_wdst[Nn];
__device__ double g_part[2048];
__device__ unsigned g_cnt = 0;

// ---- packed f32x2 helpers ------------------------------------------------
__device__ __forceinline__ unsigned long long pk2(float x, float y) {
    unsigned long long r;
    asm("mov.b64 %0, {%1, %2};" : "=l"(r) : "f"(x), "f"(y));
    return r;
}
__device__ __forceinline__ void upk2(unsigned long long v, float& x, float& y) {
    asm("mov.b64 {%0, %1}, %2;" : "=f"(x), "=f"(y) : "l"(v));
}
__device__ __forceinline__ unsigned long long ffma2(unsigned long long a,
                                                    unsigned long long b,
                                                    unsigned long long c) {
    unsigned long long d;
    asm("fma.rn.f32x2 %0, %1, %2, %3;" : "=l"(d) : "l"(a), "l"(b), "l"(c));
    return d;
}

// ---------------------------------------------------------------------------
// K0: impulse responses of both IIR filters (delta input through DFII-T)
// ---------------------------------------------------------------------------
__global__ void k_impulse(const float* __restrict__ bhi, const float* __restrict__ ahi,
                          const float* __restrict__ blo, const float* __restrict__ alo)
{
    int f = threadIdx.x;
    if (f >= 2) return;
    const float* bc = f ? bhi : blo;
    const float* ac = f ? ahi : alo;
    float inv = 1.0f / ac[0];
    float b0 = bc[0]*inv, b1 = bc[1]*inv, b2 = bc[2]*inv,
          b3 = bc[3]*inv, b4 = bc[4]*inv, b5 = bc[5]*inv;
    float a1 = ac[1]*inv, a2 = ac[2]*inv, a3 = ac[3]*inv,
          a4 = ac[4]*inv, a5 = ac[5]*inv;
    float z0=0.f, z1=0.f, z2=0.f, z3=0.f, z4=0.f;
    for (int d = 0; d < 256; d++) {
        float xv = (d == 0) ? 1.0f : 0.0f;
        float y  = fmaf(b0, xv, z0);
        z0 = fmaf(-a1, y, fmaf(b1, xv, z1));
        z1 = fmaf(-a2, y, fmaf(b2, xv, z2));
        z2 = fmaf(-a3, y, fmaf(b3, xv, z3));
        z3 = fmaf(-a4, y, fmaf(b4, xv, z4));
        z4 = fmaf(-a5, y, b5 * xv);
        g_h[f][d] = y;
    }
}

// ---------------------------------------------------------------------------
// K1: fold IIR into W1:  Wt[combo][k][c] = sum_{d>=k} h_f[d-k] * W1_br[d][c]
// grid = (16 kblocks, 4 combos), block = 64 threads (one per c)
// ---------------------------------------------------------------------------
__global__ void __launch_bounds__(64) k_fold(
    const float* __restrict__ w1s, const float* __restrict__ w1d)
{
    __shared__ float hs[256];
    int combo = blockIdx.y;
    int f  = combo & 1;
    int br = combo >> 1;
    int k0 = blockIdx.x * 16;
    int c  = threadIdx.x;
    for (int d = c; d < 256; d += 64) hs[d] = g_h[f][d];
    __syncthreads();

    const float* W1 = br ? w1d : w1s;
    float acc[16];
#pragma unroll
    for (int kk = 0; kk < 16; kk++) acc[kk] = 0.f;
    for (int d = k0; d < 256; d++) {
        float wv = __ldg(W1 + d*64 + c);
#pragma unroll
        for (int kk = 0; kk < 16; kk++) {
            int k = k0 + kk;
            if (d >= k) acc[kk] = fmaf(hs[d - k], wv, acc[kk]);
        }
    }
#pragma unroll
    for (int kk = 0; kk < 16; kk++)
        g_wt[(combo * 256 + k0 + kk) * 64 + c] = acc[kk];
}

// ---------------------------------------------------------------------------
// K2: gathered GEMM [128 rows x 64 cols] tiles, K=256, + relu/w2 epilogue.
// Segments: per branch br: 313 lo-blocks (pos 0..40K), 79 hi-blocks (40K..50K).
// Thread (i=t>>3, j=t&7): rows 8i..8i+7, cols 8j..8j+7 (4 f32x2 pairs).
// ---------------------------------------------------------------------------
#define NB_LO 313
#define NB_HI 79
#define NB_BR (NB_LO + NB_HI)   // 392
#define AS_LD 132                // 128 rows + pad, 16B-aligned stride

__global__ void __launch_bounds__(128) k_gemm(
    const float* __restrict__ x,
    const float* __restrict__ b1s, const float* __restrict__ b1d,
    const float* __restrict__ w2s, const float* __restrict__ w2d,
    const float* __restrict__ b2s, const float* __restrict__ b2d,
    const int* __restrict__ isl, const int* __restrict__ ish,
    const int* __restrict__ idl, const int* __restrict__ idh)
{
    __shared__ float As[32 * AS_LD];   // A chunk, k-major transposed: As[k][row]
    __shared__ float Ws[32 * 64];      // W chunk [k][64]
    __shared__ int   nids[128];

    int t = threadIdx.x;
    int bx = blockIdx.x;
    int br = bx / NB_BR;
    int r  = bx - br * NB_BR;
    int f, pos0, lim;
    if (r < NB_LO) { f = 0; pos0 = r * 128;                 lim = NLO; }
    else           { f = 1; pos0 = (r - NB_LO) * 128;       lim = NHI; }
    int combo = br * 2 + f;
    const int* idx = f ? (br ? idh : ish) : (br ? idl : isl);

    if (t < 128) {
        int p = pos0 + t;
        nids[t] = (p < lim) ? __ldg(idx + p) : 0;
    }

    int i = t >> 3, j = t & 7;
    int w = t >> 5, l = t & 31;

    unsigned long long acc[8][4];
#pragma unroll
    for (int rr = 0; rr < 8; rr++)
#pragma unroll
        for (int pp = 0; pp < 4; pp++) acc[rr][pp] = 0ull;

    const float* wt = g_wt + combo * 256 * 64;

    for (int kc = 0; kc < 256; kc += 32) {
        __syncthreads();
        // stage W chunk: 2048 floats
#pragma unroll
        for (int q = 0; q < 4; q++) {
            int idx4 = t + 128 * q;
            int kk = idx4 >> 4, c4 = (idx4 & 15) << 2;
            *(float4*)&Ws[kk * 64 + c4] = *(const float4*)(wt + (kc + kk) * 64 + c4);
        }
        // stage A chunk gathered, transposed to As[k][row]
#pragma unroll
        for (int it = 0; it < 8; it++) {
            int row  = w * 32 + it * 4 + (l >> 3);
            int kseg = l & 7;
            float4 v = *(const float4*)(x + (size_t)nids[row] * 256 + kc + kseg * 4);
            As[(kseg*4 + 0) * AS_LD + row] = v.x;
            As[(kseg*4 + 1) * AS_LD + row] = v.y;
            As[(kseg*4 + 2) * AS_LD + row] = v.z;
            As[(kseg*4 + 3) * AS_LD + row] = v.w;
        }
        __syncthreads();

#pragma unroll 8
        for (int kk = 0; kk < 32; kk++) {
            float4 a0 = *(const float4*)&As[kk * AS_LD + 8*i];
            float4 a1 = *(const float4*)&As[kk * AS_LD + 8*i + 4];
            ulonglong2 w01 = *(const ulonglong2*)&Ws[kk * 64 + 8*j];
            ulonglong2 w23 = *(const ulonglong2*)&Ws[kk * 64 + 8*j + 4];
            float af[8] = {a0.x, a0.y, a0.z, a0.w, a1.x, a1.y, a1.z, a1.w};
#pragma unroll
            for (int rr = 0; rr < 8; rr++) {
                unsigned long long a2 = pk2(af[rr], af[rr]);
                acc[rr][0] = ffma2(a2, w01.x, acc[rr][0]);
                acc[rr][1] = ffma2(a2, w01.y, acc[rr][1]);
                acc[rr][2] = ffma2(a2, w23.x, acc[rr][2]);
                acc[rr][3] = ffma2(a2, w23.y, acc[rr][3]);
            }
        }
    }

    // epilogue: relu(h + b1) . w2 over this thread's 8 cols, reduce across j
    const float* b1p = br ? b1d : b1s;
    const float* w2p = br ? w2d : w2s;
    float b1v[8], w2v[8];
#pragma unroll
    for (int cc = 0; cc < 8; cc++) {
        b1v[cc] = __ldg(b1p + 8*j + cc);
        w2v[cc] = __ldg(w2p + 8*j + cc);
    }
    float b2v = __ldg(br ? b2d : b2s);
    float* outw = br ? g_wdst : g_wsrc;

#pragma unroll
    for (int rr = 0; rr < 8; rr++) {
        float p = 0.f;
#pragma unroll
        for (int pp = 0; pp < 4; pp++) {
            float v0, v1; upk2(acc[rr][pp], v0, v1);
            p += fmaxf(v0 + b1v[2*pp],   0.f) * w2v[2*pp]
               + fmaxf(v1 + b1v[2*pp+1], 0.f) * w2v[2*pp+1];
        }
        p += __shfl_xor_sync(0xffffffffu, p, 1);
        p += __shfl_xor_sync(0xffffffffu, p, 2);
        p += __shfl_xor_sync(0xffffffffu, p, 4);
        if (j == 0) {
            int pos = pos0 + 8*i + rr;
            if (pos < lim) outw[(f ? NLO : 0) + pos] = p + b2v;
        }
    }
}

// ---------------------------------------------------------------------------
// K3: edge gate (log-free sigmoid identity) + full deterministic reduction.
// sigmoid((logit(eps)+w)/0.5) = 1 / (1 + ((1-eps)/eps)^2 * exp(-2w))
// ---------------------------------------------------------------------------
#define NPART 1563
__global__ void __launch_bounds__(256) k_edge(
    const int* __restrict__ src, const int* __restrict__ dst,
    const float* __restrict__ u, float* __restrict__ out)
{
    __shared__ double red[256];
    __shared__ int isLast;
    int t = threadIdx.x;
    int base = (blockIdx.x * 256 + t) * 4;
    double local = 0.0;
    if (base < Ee) {  // Ee % 4 == 0
        int4   s4 = *(const int4*)(src + base);
        int4   d4 = *(const int4*)(dst + base);
        float4 u4 = *(const float4*)(u + base);
        float wv[4] = { __ldg(&g_wsrc[s4.x]) + __ldg(&g_wdst[d4.x]),
                        __ldg(&g_wsrc[s4.y]) + __ldg(&g_wdst[d4.y]),
                        __ldg(&g_wsrc[s4.z]) + __ldg(&g_wdst[d4.z]),
                        __ldg(&g_wsrc[s4.w]) + __ldg(&g_wdst[d4.w]) };
        float uu[4] = { u4.x, u4.y, u4.z, u4.w };
#pragma unroll
        for (int q = 0; q < 4; q++) {
            float eps  = 0.9999f - 0.9998f * uu[q];
            float onem = 0.0001f + 0.9998f * uu[q];      // 1 - eps
            float rr   = __fdividef(onem, eps);
            float ge   = __expf(-2.0f * wv[q]);
            float aug  = __fdividef(1.0f, fmaf(rr * rr, ge, 1.0f));
            out[1 + base + q] = aug;
            local += (double)aug;
        }
    }
    red[t] = local;
    __syncthreads();
    for (int off = 128; off; off >>= 1) {
        if (t < off) red[t] += red[t + off];
        __syncthreads();
    }
    if (t == 0) {
        g_part[blockIdx.x] = red[0];
        __threadfence();
        unsigned old = atomicAdd(&g_cnt, 1u);
        isLast = (old == NPART - 1);
    }
    __syncthreads();
    if (isLast) {
        double l2 = 0.0;
        for (int idx = t; idx < NPART; idx += 256) l2 += g_part[idx];
        red[t] = l2;
        __syncthreads();
        for (int off = 128; off; off >>= 1) {
            if (t < off) red[t] += red[t + off];
            __syncthreads();
        }
        if (t == 0) {
            out[0] = (float)(1.0 - red[0] / (double)Ee);
            g_cnt = 0;
        }
    }
}

// ---------------------------------------------------------------------------
extern "C" void kernel_launch(void* const* d_in, const int* in_sizes, int n_in,
                              void* d_out, int out_size)
{
    const float* node_emb = (const float*)d_in[0];
    const float* w1_src   = (const float*)d_in[1];
    const float* b1_src   = (const float*)d_in[2];
    const float* w2_src   = (const float*)d_in[3];
    const float* b2_src   = (const float*)d_in[4];
    const float* w1_dst   = (const float*)d_in[5];
    const float* b1_dst   = (const float*)d_in[6];
    const float* w2_dst   = (const float*)d_in[7];
    const float* b2_dst   = (const float*)d_in[8];
    const float* b_hi     = (const float*)d_in[9];
    const float* a_hi     = (const float*)d_in[10];
    const float* b_lo     = (const float*)d_in[11];
    const float* a_lo     = (const float*)d_in[12];
    const float* u_eps    = (const float*)d_in[13];
    const int*   src      = (const int*)d_in[14];
    const int*   dst      = (const int*)d_in[15];
    const int*   idx_src_hi = (const int*)d_in[16];
    const int*   idx_src_lo = (const int*)d_in[17];
    const int*   idx_dst_hi = (const int*)d_in[18];
    const int*   idx_dst_lo = (const int*)d_in[19];
    float* out = (float*)d_out;

    k_impulse<<<1, 32>>>(b_hi, a_hi, b_lo, a_lo);
    dim3 gfold(16, 4);
    k_fold<<<gfold, 64>>>(w1_src, w1_dst);
    k_gemm<<<2 * NB_BR, 128>>>(node_emb, b1_src, b1_dst, w2_src, w2_dst,
                               b2_src, b2_dst,
                               idx_src_lo, idx_src_hi, idx_dst_lo, idx_dst_hi);
    k_edge<<<NPART, 256>>>(src, dst, u_eps, out);
}

// round 5
// speedup vs baseline: 2.7166x; 1.1930x over previous
#include <cuda_runtime.h>
#include <math.h>

#define Nn 50000
#define Ee 1600000
#define NLO 40000
#define NHI 10000

// Scratch
__device__ float g_wt[4 * 256 * 64];     // folded W1: combo = br*2+f, [k][c]
__device__ float g_wsrc[Nn];
__device__ float g_wdst[Nn];
__device__ double g_part[2048];
__device__ unsigned g_cnt = 0;

// ---- packed f32x2 helpers ------------------------------------------------
__device__ __forceinline__ unsigned long long pk2(float x, float y) {
    unsigned long long r;
    asm("mov.b64 %0, {%1, %2};" : "=l"(r) : "f"(x), "f"(y));
    return r;
}
__device__ __forceinline__ void upk2(unsigned long long v, float& x, float& y) {
    asm("mov.b64 {%0, %1}, %2;" : "=f"(x), "=f"(y) : "l"(v));
}
__device__ __forceinline__ unsigned long long ffma2(unsigned long long a,
                                                    unsigned long long b,
                                                    unsigned long long c) {
    unsigned long long d;
    asm("fma.rn.f32x2 %0, %1, %2, %3;" : "=l"(d) : "l"(a), "l"(b), "l"(c));
    return d;
}

// ---- cp.async helpers -----------------------------------------------------
__device__ __forceinline__ void cpa16(void* dst_smem, const void* src_gmem) {
    unsigned d = (unsigned)__cvta_generic_to_shared(dst_smem);
    asm volatile("cp.async.cg.shared.global [%0], [%1], 16;"
                 :: "r"(d), "l"(src_gmem));
}
__device__ __forceinline__ void cpa_commit() {
    asm volatile("cp.async.commit_group;");
}
template<int NWAIT>
__device__ __forceinline__ void cpa_wait() {
    asm volatile("cp.async.wait_group %0;" :: "n"(NWAIT));
}

// ---------------------------------------------------------------------------
// K1: impulse response + fold IIR into W1:
//   Wt[combo][k][c] = sum_{d>=k} h_f[d-k] * W1_br[d][c]
// grid = (64 kblocks of 4, 4 combos), block = 64 threads (one per c)
// ---------------------------------------------------------------------------
__global__ void __launch_bounds__(64) k_fold(
    const float* __restrict__ w1s, const float* __restrict__ w1d,
    const float* __restrict__ bhi, const float* __restrict__ ahi,
    const float* __restrict__ blo, const float* __restrict__ alo)
{
    __shared__ float hs[256];
    int combo = blockIdx.y;
    int f  = combo & 1;
    int br = combo >> 1;
    int k0 = blockIdx.x * 4;
    int c  = threadIdx.x;

    if (c == 0) {   // impulse response of this block's filter (serial, ~2K cyc)
        const float* bc = f ? bhi : blo;
        const float* ac = f ? ahi : alo;
        float inv = 1.0f / ac[0];
        float b0 = bc[0]*inv, b1 = bc[1]*inv, b2 = bc[2]*inv,
              b3 = bc[3]*inv, b4 = bc[4]*inv, b5 = bc[5]*inv;
        float a1 = ac[1]*inv, a2 = ac[2]*inv, a3 = ac[3]*inv,
              a4 = ac[4]*inv, a5 = ac[5]*inv;
        float z0=0.f, z1=0.f, z2=0.f, z3=0.f, z4=0.f;
        for (int d = 0; d < 256; d++) {
            float xv = (d == 0) ? 1.0f : 0.0f;
            float y  = fmaf(b0, xv, z0);
            z0 = fmaf(-a1, y, fmaf(b1, xv, z1));
            z1 = fmaf(-a2, y, fmaf(b2, xv, z2));
            z2 = fmaf(-a3, y, fmaf(b3, xv, z3));
            z3 = fmaf(-a4, y, fmaf(b4, xv, z4));
            z4 = fmaf(-a5, y, b5 * xv);
            hs[d] = y;
        }
    }
    __syncthreads();

    const float* W1 = br ? w1d : w1s;
    float acc[4] = {0.f, 0.f, 0.f, 0.f};
    for (int d = k0; d < 256; d++) {
        float wv = __ldg(W1 + d*64 + c);
#pragma unroll
        for (int kk = 0; kk < 4; kk++)
            if (d >= k0 + kk) acc[kk] = fmaf(hs[d - (k0 + kk)], wv, acc[kk]);
    }
#pragma unroll
    for (int kk = 0; kk < 4; kk++)
        g_wt[(combo * 256 + k0 + kk) * 64 + c] = acc[kk];
}

// ---------------------------------------------------------------------------
// K2: gathered GEMM, 128 rows x 64 cols tile, K=256, cp.async double-buffered.
// 256 threads. Thread (i=t>>3, j=t&7): rows 4i..4i+3, cols 8j..8j+7.
// ---------------------------------------------------------------------------
#define NB_LO 313
#define NB_HI 79
#define NB_BR (NB_LO + NB_HI)   // 392
#define KCH 16
#define NCHUNK 16
#define A_LD 20                  // 16 floats + 4 pad (80B rows, 16B aligned)

__global__ void __launch_bounds__(256) k_gemm(
    const float* __restrict__ x,
    const float* __restrict__ b1s, const float* __restrict__ b1d,
    const float* __restrict__ w2s, const float* __restrict__ w2d,
    const float* __restrict__ b2s, const float* __restrict__ b2d,
    const int* __restrict__ isl, const int* __restrict__ ish,
    const int* __restrict__ idl, const int* __restrict__ idh)
{
    __shared__ float As[2][128 * A_LD];
    __shared__ float Ws[2][KCH * 64];
    __shared__ int   nids[128];

    int t = threadIdx.x;
    int bx = blockIdx.x;
    int br = bx / NB_BR;
    int r  = bx - br * NB_BR;
    int f, pos0, lim;
    if (r < NB_LO) { f = 0; pos0 = r * 128;            lim = NLO; }
    else           { f = 1; pos0 = (r - NB_LO) * 128;  lim = NHI; }
    int combo = br * 2 + f;
    const int* idx = f ? (br ? idh : ish) : (br ? idl : isl);
    const float* wt = g_wt + combo * 256 * 64;

    if (t < 128) {
        int p = pos0 + t;
        nids[t] = (p < lim) ? __ldg(idx + p) : 0;
    }
    __syncthreads();

    int i = t >> 3, j = t & 7;

    unsigned long long acc[4][4];
#pragma unroll
    for (int rr = 0; rr < 4; rr++)
#pragma unroll
        for (int pp = 0; pp < 4; pp++) acc[rr][pp] = 0ull;

    // ---- staging macro: chunk c into buffer c&1 ----
#define STAGE(c) do {                                                         \
        int buf = (c) & 1;                                                    \
        int kc  = (c) * KCH;                                                  \
        /* A: 512x16B, 2 per thread */                                        \
        {   int idx0 = t;            int row0 = idx0 >> 2, s0 = idx0 & 3;     \
            cpa16(&As[buf][row0 * A_LD + s0 * 4],                             \
                  x + (size_t)nids[row0] * 256 + kc + s0 * 4);                \
            int idx1 = t + 256;      int row1 = idx1 >> 2, s1 = idx1 & 3;     \
            cpa16(&As[buf][row1 * A_LD + s1 * 4],                             \
                  x + (size_t)nids[row1] * 256 + kc + s1 * 4);                \
        }                                                                     \
        /* W: 256x16B, 1 per thread */                                        \
        cpa16(&Ws[buf][t * 4], wt + kc * 64 + t * 4);                         \
        cpa_commit();                                                         \
    } while (0)

    STAGE(0);

    for (int c = 0; c < NCHUNK; c++) {
        if (c + 1 < NCHUNK) { STAGE(c + 1); cpa_wait<1>(); }
        else                { cpa_wait<0>(); }
        __syncthreads();

        int buf = c & 1;
        const float* a_base = &As[buf][(4 * i) * A_LD];
        const float* w_base = &Ws[buf][0];

#pragma unroll
        for (int g = 0; g < 4; g++) {
            float4 ar[4];
#pragma unroll
            for (int rr = 0; rr < 4; rr++)
                ar[rr] = *(const float4*)(a_base + rr * A_LD + g * 4);
#pragma unroll
            for (int q = 0; q < 4; q++) {
                int kk = g * 4 + q;
                ulonglong2 w01 = *(const ulonglong2*)(w_base + kk * 64 + 8*j);
                ulonglong2 w23 = *(const ulonglong2*)(w_base + kk * 64 + 8*j + 4);
#pragma unroll
                for (int rr = 0; rr < 4; rr++) {
                    float a = (q == 0) ? ar[rr].x : (q == 1) ? ar[rr].y
                            : (q == 2) ? ar[rr].z : ar[rr].w;
                    unsigned long long a2 = pk2(a, a);
                    acc[rr][0] = ffma2(a2, w01.x, acc[rr][0]);
                    acc[rr][1] = ffma2(a2, w01.y, acc[rr][1]);
                    acc[rr][2] = ffma2(a2, w23.x, acc[rr][2]);
                    acc[rr][3] = ffma2(a2, w23.y, acc[rr][3]);
                }
            }
        }
        __syncthreads();
    }
#undef STAGE

    // epilogue: relu(h + b1) . w2 over this thread's 8 cols, reduce across j
    const float* b1p = br ? b1d : b1s;
    const float* w2p = br ? w2d : w2s;
    float b1v[8], w2v[8];
#pragma unroll
    for (int cc = 0; cc < 8; cc++) {
        b1v[cc] = __ldg(b1p + 8*j + cc);
        w2v[cc] = __ldg(w2p + 8*j + cc);
    }
    float b2v = __ldg(br ? b2d : b2s);
    float* outw = br ? g_wdst : g_wsrc;

#pragma unroll
    for (int rr = 0; rr < 4; rr++) {
        float p = 0.f;
#pragma unroll
        for (int pp = 0; pp < 4; pp++) {
            float v0, v1; upk2(acc[rr][pp], v0, v1);
            p += fmaxf(v0 + b1v[2*pp],   0.f) * w2v[2*pp]
               + fmaxf(v1 + b1v[2*pp+1], 0.f) * w2v[2*pp+1];
        }
        p += __shfl_xor_sync(0xffffffffu, p, 1);
        p += __shfl_xor_sync(0xffffffffu, p, 2);
        p += __shfl_xor_sync(0xffffffffu, p, 4);
        if (j == 0) {
            int pos = pos0 + 4*i + rr;
            if (pos < lim) outw[(f ? NLO : 0) + pos] = p + b2v;
        }
    }
}

// ---------------------------------------------------------------------------
// K3: edge gate, 8 edges/thread (2 float4 groups), log-free sigmoid identity,
// + deterministic two-level reduction with last-block finish.
// sigmoid((logit(eps)+w)/0.5) = 1 / (1 + ((1-eps)/eps)^2 * exp(-2w))
// ---------------------------------------------------------------------------
#define EDGES_PER_BLOCK 2048
#define NPART 782   // ceil(1.6M / 2048)

__device__ __forceinline__ double edge_quad(
    const int* __restrict__ src, const int* __restrict__ dst,
    const float* __restrict__ u, float* __restrict__ out, int base)
{
    int4   s4 = *(const int4*)(src + base);
    int4   d4 = *(const int4*)(dst + base);
    float4 u4 = *(const float4*)(u + base);
    float wv[4] = { __ldg(&g_wsrc[s4.x]) + __ldg(&g_wdst[d4.x]),
                    __ldg(&g_wsrc[s4.y]) + __ldg(&g_wdst[d4.y]),
                    __ldg(&g_wsrc[s4.z]) + __ldg(&g_wdst[d4.z]),
                    __ldg(&g_wsrc[s4.w]) + __ldg(&g_wdst[d4.w]) };
    float uu[4] = { u4.x, u4.y, u4.z, u4.w };
    double local = 0.0;
#pragma unroll
    for (int q = 0; q < 4; q++) {
        float eps  = 0.9999f - 0.9998f * uu[q];
        float onem = 0.0001f + 0.9998f * uu[q];      // 1 - eps
        float rr   = __fdividef(onem, eps);
        float ge   = __expf(-2.0f * wv[q]);
        float aug  = __fdividef(1.0f, fmaf(rr * rr, ge, 1.0f));
        out[1 + base + q] = aug;
        local += (double)aug;
    }
    return local;
}

__global__ void __launch_bounds__(256) k_edge(
    const int* __restrict__ src, const int* __restrict__ dst,
    const float* __restrict__ u, float* __restrict__ out)
{
    __shared__ double red[256];
    __shared__ int isLast;
    int t = threadIdx.x;
    int blk0 = blockIdx.x * EDGES_PER_BLOCK;
    double local = 0.0;
    int b0 = blk0 + t * 4;
    int b1 = blk0 + 1024 + t * 4;
    if (b0 < Ee) local += edge_quad(src, dst, u, out, b0);
    if (b1 < Ee) local += edge_quad(src, dst, u, out, b1);

    red[t] = local;
    __syncthreads();
    for (int off = 128; off; off >>= 1) {
        if (t < off) red[t] += red[t + off];
        __syncthreads();
    }
    if (t == 0) {
        g_part[blockIdx.x] = red[0];
        __threadfence();
        unsigned old = atomicAdd(&g_cnt, 1u);
        isLast = (old == NPART - 1);
    }
    __syncthreads();
    if (isLast) {
        double l2 = 0.0;
        for (int idx = t; idx < NPART; idx += 256) l2 += g_part[idx];
        red[t] = l2;
        __syncthreads();
        for (int off = 128; off; off >>= 1) {
            if (t < off) red[t] += red[t + off];
            __syncthreads();
        }
        if (t == 0) {
            out[0] = (float)(1.0 - red[0] / (double)Ee);
            g_cnt = 0;
        }
    }
}

// ---------------------------------------------------------------------------
extern "C" void kernel_launch(void* const* d_in, const int* in_sizes, int n_in,
                              void* d_out, int out_size)
{
    const float* node_emb = (const float*)d_in[0];
    const float* w1_src   = (const float*)d_in[1];
    const float* b1_src   = (const float*)d_in[2];
    const float* w2_src   = (const float*)d_in[3];
    const float* b2_src   = (const float*)d_in[4];
    const float* w1_dst   = (const float*)d_in[5];
    const float* b1_dst   = (const float*)d_in[6];
    const float* w2_dst   = (const float*)d_in[7];
    const float* b2_dst   = (const float*)d_in[8];
    const float* b_hi     = (const float*)d_in[9];
    const float* a_hi     = (const float*)d_in[10];
    const float* b_lo     = (const float*)d_in[11];
    const float* a_lo     = (const float*)d_in[12];
    const float* u_eps    = (const float*)d_in[13];
    const int*   src      = (const int*)d_in[14];
    const int*   dst      = (const int*)d_in[15];
    const int*   idx_src_hi = (const int*)d_in[16];
    const int*   idx_src_lo = (const int*)d_in[17];
    const int*   idx_dst_hi = (const int*)d_in[18];
    const int*   idx_dst_lo = (const int*)d_in[19];
    float* out = (float*)d_out;

    dim3 gfold(64, 4);
    k_fold<<<gfold, 64>>>(w1_src, w1_dst, b_hi, a_hi, b_lo, a_lo);
    k_gemm<<<2 * NB_BR, 256>>>(node_emb, b1_src, b1_dst, w2_src, w2_dst,
                               b2_src, b2_dst,
                               idx_src_lo, idx_src_hi, idx_dst_lo, idx_dst_hi);
    k_edge<<<NPART, 256>>>(src, dst, u_eps, out);
}

// round 10
// speedup vs baseline: 3.7153x; 1.3676x over previous
#include <cuda_runtime.h>
#include <cuda_bf16.h>
#include <math.h>
#include <cstdint>

#define Nn 50000
#define Ee 1600000
#define NLO 40000
#define NHI 10000

// ---------------------------------------------------------------------------
// Scratch (static device arrays)
// ---------------------------------------------------------------------------
__device__ float g_h[2][256];                 // impulse responses lo/hi
// Folded W1, split bf16, packed in mma B-fragment order:
// [combo(4)][var(2: hi,lo)][word = ks*512 + nt*64 + r*32 + lane]
__device__ uint32_t g_wtf[4][2][8192];
__device__ float g_wsrc[Nn];
__device__ float g_wdst[Nn];
__device__ double g_part[2048];
__device__ unsigned g_cnt = 0;

// ---------------------------------------------------------------------------
// cp.async helpers (Ampere+, fine on sm_100)
// ---------------------------------------------------------------------------
__device__ __forceinline__ void cpa16(void* dst_smem, const void* src_gmem) {
    unsigned d = (unsigned)__cvta_generic_to_shared(dst_smem);
    asm volatile("cp.async.cg.shared.global [%0], [%1], 16;" :: "r"(d), "l"(src_gmem));
}
__device__ __forceinline__ void cpa_commit() { asm volatile("cp.async.commit_group;"); }
template<int NW> __device__ __forceinline__ void cpa_wait() {
    asm volatile("cp.async.wait_group %0;" :: "n"(NW));
}

// ---------------------------------------------------------------------------
// bf16 mma.sync m16n8k16 (sm_80+; runs on tensor pipes on sm_100)
// ---------------------------------------------------------------------------
__device__ __forceinline__ void mma16816(float* c, const uint32_t* a,
                                         uint32_t b0, uint32_t b1) {
    asm volatile(
        "mma.sync.aligned.m16n8k16.row.col.f32.bf16.bf16.f32 "
        "{%0,%1,%2,%3}, {%4,%5,%6,%7}, {%8,%9}, {%0,%1,%2,%3};"
        : "+f"(c[0]), "+f"(c[1]), "+f"(c[2]), "+f"(c[3])
        : "r"(a[0]), "r"(a[1]), "r"(a[2]), "r"(a[3]), "r"(b0), "r"(b1));
}

// ---------------------------------------------------------------------------
// K0: impulse responses (tiny serial kernel, once)
// ---------------------------------------------------------------------------
__global__ void k_imp(const float* __restrict__ bhi, const float* __restrict__ ahi,
                      const float* __restrict__ blo, const float* __restrict__ alo)
{
    int f = threadIdx.x;
    if (f >= 2) return;
    const float* bc = f ? bhi : blo;
    const float* ac = f ? ahi : alo;
    float inv = 1.0f / ac[0];
    float b0 = bc[0]*inv, b1 = bc[1]*inv, b2 = bc[2]*inv,
          b3 = bc[3]*inv, b4 = bc[4]*inv, b5 = bc[5]*inv;
    float a1 = ac[1]*inv, a2 = ac[2]*inv, a3 = ac[3]*inv,
          a4 = ac[4]*inv, a5 = ac[5]*inv;
    float z0=0.f, z1=0.f, z2=0.f, z3=0.f, z4=0.f;
    for (int d = 0; d < 256; d++) {
        float xv = (d == 0) ? 1.0f : 0.0f;
        float y  = fmaf(b0, xv, z0);
        z0 = fmaf(-a1, y, fmaf(b1, xv, z1));
        z1 = fmaf(-a2, y, fmaf(b2, xv, z2));
        z2 = fmaf(-a3, y, fmaf(b3, xv, z3));
        z3 = fmaf(-a4, y, fmaf(b4, xv, z4));
        z4 = fmaf(-a5, y, b5 * xv);
        g_h[f][d] = y;
    }
}

// ---------------------------------------------------------------------------
// K1: fold IIR into W1 and pack as split-bf16 mma B-fragments.
//   wt(combo,k,n) = sum_{d>=k} h_f[d-k] * W1_br[d][n]
// grid (64, 4 combos), block 256: k = bx*4 + t/64, n = t%64
// Fragment mapping (m16n8k16 B, col-major):
//   ks=k>>4, kr=k&15, r=kr>>3, p=kr&1, lane=(n&7)*4+((kr&7)>>1), nt=n>>3
// ---------------------------------------------------------------------------
__global__ void __launch_bounds__(256) k_fold(
    const float* __restrict__ w1s, const float* __restrict__ w1d)
{
    __shared__ float hs[256];
    int combo = blockIdx.y;
    int f  = combo & 1;
    int br = combo >> 1;
    int t  = threadIdx.x;
    int k  = blockIdx.x * 4 + (t >> 6);
    int n  = t & 63;
    for (int d = t; d < 256; d += 256) hs[d] = g_h[f][d];
    __syncthreads();

    const float* W1 = br ? w1d : w1s;
    float acc = 0.f;
    for (int d = k; d < 256; d++)
        acc = fmaf(hs[d - k], __ldg(W1 + d*64 + n), acc);

    __nv_bfloat16 hi = __float2bfloat16(acc);
    __nv_bfloat16 lo = __float2bfloat16(acc - __bfloat162float(hi));

    int ks = k >> 4, kr = k & 15;
    int r  = kr >> 3, p = kr & 1;
    int lane = (n & 7) * 4 + ((kr & 7) >> 1);
    int nt = n >> 3;
    int word = ks * 512 + nt * 64 + r * 32 + lane;
    ((__nv_bfloat16*)g_wtf[combo][0])[word * 2 + p] = hi;
    ((__nv_bfloat16*)g_wtf[combo][1])[word * 2 + p] = lo;
}

// ---------------------------------------------------------------------------
// K2: gathered split-bf16 HMMA GEMM + fused relu/w2 epilogue.
// Block: 256 threads / 8 warps; tile 128 gathered rows x 64 cols; K=256.
// Warp w owns rows [16w,16w+16), all 8 n-tiles (32 fp32 accums).
// A: fp32 gathered via cp.async (KC=32, double-buffered), converted to
// bf16 hi/lo in registers per k-step. W: fragment LDGs (L1/L2-resident).
// ---------------------------------------------------------------------------
#define NB_LO 313
#define NB_HI 79
#define NB_BR 392
#define KC 32
#define A_LD 36   // 144B row stride: 16B-aligned, conflict-free frag reads

__global__ void __launch_bounds__(256) k_gemm(
    const float* __restrict__ x,
    const float* __restrict__ b1s, const float* __restrict__ b1d,
    const float* __restrict__ w2s, const float* __restrict__ w2d,
    const float* __restrict__ b2s, const float* __restrict__ b2d,
    const int* __restrict__ isl, const int* __restrict__ ish,
    const int* __restrict__ idl, const int* __restrict__ idh)
{
    __shared__ float As[2][128 * A_LD];
    __shared__ int nids[128];

    int t = threadIdx.x;
    int warp = t >> 5, lane = t & 31;

    int bx = blockIdx.x;
    int br = bx / NB_BR;
    int r  = bx - br * NB_BR;
    int f, pos0, lim;
    if (r < NB_LO) { f = 0; pos0 = r * 128;            lim = NLO; }
    else           { f = 1; pos0 = (r - NB_LO) * 128;  lim = NHI; }
    int combo = br * 2 + f;
    const int* idx = f ? (br ? idh : ish) : (br ? idl : isl);

    if (t < 128) {
        int p = pos0 + t;
        nids[t] = (p < lim) ? __ldg(idx + p) : 0;
    }
    __syncthreads();

    const uint32_t* Whi = g_wtf[combo][0];
    const uint32_t* Wlo = g_wtf[combo][1];

    float acc[8][4];
#pragma unroll
    for (int nt = 0; nt < 8; nt++)
#pragma unroll
        for (int q = 0; q < 4; q++) acc[nt][q] = 0.f;

    // A tile: 128 rows x KC(=32) floats = 1024 float4s; 8 segs per row.
    // u in [0,1024): row = u>>3 (0..127), seg = u&7 (0..7) -> col seg*4.
#define STAGE(c) do { int _b = (c) & 1; int _kc = (c) * KC;                   \
        _Pragma("unroll")                                                     \
        for (int q = 0; q < 4; q++) {                                         \
            int u = t + 256*q; int row = u >> 3, seg = u & 7;                 \
            cpa16(&As[_b][row * A_LD + seg * 4],                              \
                  x + (size_t)nids[row] * 256 + _kc + seg * 4);               \
        }                                                                     \
        cpa_commit(); } while (0)

    STAGE(0);

#pragma unroll 1
    for (int c = 0; c < 8; c++) {
        if (c + 1 < 8) { STAGE(c + 1); cpa_wait<1>(); }
        else           { cpa_wait<0>(); }
        __syncthreads();

        const float* Ab = &As[c & 1][(warp * 16) * A_LD];
        int rrow = lane >> 2;           // 0..7
        int kp   = (lane & 3) * 2;      // 0,2,4,6

#pragma unroll
        for (int s = 0; s < 2; s++) {
            int kb = s * 16;
            float2 f0 = *(const float2*)(Ab + rrow * A_LD + kb + kp);
            float2 f1 = *(const float2*)(Ab + (rrow + 8) * A_LD + kb + kp);
            float2 f2 = *(const float2*)(Ab + rrow * A_LD + kb + kp + 8);
            float2 f3 = *(const float2*)(Ab + (rrow + 8) * A_LD + kb + kp + 8);

            uint32_t ahi[4], alo[4];
            float2 fs[4] = {f0, f1, f2, f3};
#pragma unroll
            for (int i = 0; i < 4; i++) {
                __nv_bfloat162 hp;
                hp.x = __float2bfloat16(fs[i].x);
                hp.y = __float2bfloat16(fs[i].y);
                __nv_bfloat162 lp;
                lp.x = __float2bfloat16(fs[i].x - __bfloat162float(hp.x));
                lp.y = __float2bfloat16(fs[i].y - __bfloat162float(hp.y));
                ahi[i] = *(uint32_t*)&hp;
                alo[i] = *(uint32_t*)&lp;
            }

            int ksg = c * 2 + s;
            const uint32_t* whb = Whi + ksg * 512 + lane;
            const uint32_t* wlb = Wlo + ksg * 512 + lane;
#pragma unroll
            for (int nt = 0; nt < 8; nt++) {
                uint32_t h0 = __ldg(whb + nt * 64);
                uint32_t h1 = __ldg(whb + nt * 64 + 32);
                uint32_t l0 = __ldg(wlb + nt * 64);
                uint32_t l1 = __ldg(wlb + nt * 64 + 32);
                mma16816(acc[nt], ahi, h0, h1);
                mma16816(acc[nt], ahi, l0, l1);
                mma16816(acc[nt], alo, h0, h1);
            }
        }
        __syncthreads();
    }
#undef STAGE

    // epilogue: relu(h + b1) . w2 ; thread covers rows rA, rA+8, 2 cols/nt
    const float* b1p = br ? b1d : b1s;
    const float* w2p = br ? w2d : w2s;
    float pA = 0.f, pB = 0.f;
#pragma unroll
    for (int nt = 0; nt < 8; nt++) {
        int n0 = nt * 8 + (lane & 3) * 2;
        float ba = __ldg(b1p + n0),     bb = __ldg(b1p + n0 + 1);
        float wa = __ldg(w2p + n0),     wb = __ldg(w2p + n0 + 1);
        pA += fmaxf(acc[nt][0] + ba, 0.f) * wa + fmaxf(acc[nt][1] + bb, 0.f) * wb;
        pB += fmaxf(acc[nt][2] + ba, 0.f) * wa + fmaxf(acc[nt][3] + bb, 0.f) * wb;
    }
    pA += __shfl_xor_sync(0xffffffffu, pA, 1);
    pA += __shfl_xor_sync(0xffffffffu, pA, 2);
    pB += __shfl_xor_sync(0xffffffffu, pB, 1);
    pB += __shfl_xor_sync(0xffffffffu, pB, 2);
    if ((lane & 3) == 0) {
        float b2v = __ldg(br ? b2d : b2s);
        float* outw = br ? g_wdst : g_wsrc;
        int base = f ? NLO : 0;
        int rowA = pos0 + warp * 16 + (lane >> 2);
        if (rowA < lim)     outw[base + rowA]     = pA + b2v;
        if (rowA + 8 < lim) outw[base + rowA + 8] = pB + b2v;
    }
}

// ---------------------------------------------------------------------------
// K3: edge gate, 8 edges/thread, log-free sigmoid identity, fused reduction.
// sigmoid((logit(eps)+w)/0.5) = 1 / (1 + ((1-eps)/eps)^2 * exp(-2w))
// ---------------------------------------------------------------------------
#define EDGES_PER_BLOCK 2048
#define NPART 782

__device__ __forceinline__ double edge_quad(
    const int* __restrict__ src, const int* __restrict__ dst,
    const float* __restrict__ u, float* __restrict__ out, int base)
{
    int4   s4 = *(const int4*)(src + base);
    int4   d4 = *(const int4*)(dst + base);
    float4 u4 = *(const float4*)(u + base);
    float wv[4] = { __ldg(&g_wsrc[s4.x]) + __ldg(&g_wdst[d4.x]),
                    __ldg(&g_wsrc[s4.y]) + __ldg(&g_wdst[d4.y]),
                    __ldg(&g_wsrc[s4.z]) + __ldg(&g_wdst[d4.z]),
                    __ldg(&g_wsrc[s4.w]) + __ldg(&g_wdst[d4.w]) };
    float uu[4] = { u4.x, u4.y, u4.z, u4.w };
    double local = 0.0;
#pragma unroll
    for (int q = 0; q < 4; q++) {
        float eps  = 0.9999f - 0.9998f * uu[q];
        float onem = 0.0001f + 0.9998f * uu[q];
        float rr   = __fdividef(onem, eps);
        float ge   = __expf(-2.0f * wv[q]);
        float aug  = __fdividef(1.0f, fmaf(rr * rr, ge, 1.0f));
        out[1 + base + q] = aug;
        local += (double)aug;
    }
    return local;
}

__global__ void __launch_bounds__(256) k_edge(
    const int* __restrict__ src, const int* __restrict__ dst,
    const float* __restrict__ u, float* __restrict__ out)
{
    __shared__ double red[256];
    __shared__ int isLast;
    int t = threadIdx.x;
    int blk0 = blockIdx.x * EDGES_PER_BLOCK;
    double local = 0.0;
    int b0 = blk0 + t * 4;
    int b1 = blk0 + 1024 + t * 4;
    if (b0 < Ee) local += edge_quad(src, dst, u, out, b0);
    if (b1 < Ee) local += edge_quad(src, dst, u, out, b1);

    red[t] = local;
    __syncthreads();
    for (int off = 128; off; off >>= 1) {
        if (t < off) red[t] += red[t + off];
        __syncthreads();
    }
    if (t == 0) {
        g_part[blockIdx.x] = red[0];
        __threadfence();
        unsigned old = atomicAdd(&g_cnt, 1u);
        isLast = (old == NPART - 1);
    }
    __syncthreads();
    if (isLast) {
        double l2 = 0.0;
        for (int i = t; i < NPART; i += 256) l2 += g_part[i];
        red[t] = l2;
        __syncthreads();
        for (int off = 128; off; off >>= 1) {
            if (t < off) red[t] += red[t + off];
            __syncthreads();
        }
        if (t == 0) {
            out[0] = (float)(1.0 - red[0] / (double)Ee);
            g_cnt = 0;
        }
    }
}

// ---------------------------------------------------------------------------
extern "C" void kernel_launch(void* const* d_in, const int* in_sizes, int n_in,
                              void* d_out, int out_size)
{
    const float* node_emb = (const float*)d_in[0];
    const float* w1_src   = (const float*)d_in[1];
    const float* b1_src   = (const float*)d_in[2];
    const float* w2_src   = (const float*)d_in[3];
    const float* b2_src   = (const float*)d_in[4];
    const float* w1_dst   = (const float*)d_in[5];
    const float* b1_dst   = (const float*)d_in[6];
    const float* w2_dst   = (const float*)d_in[7];
    const float* b2_dst   = (const float*)d_in[8];
    const float* b_hi     = (const float*)d_in[9];
    const float* a_hi     = (const float*)d_in[10];
    const float* b_lo     = (const float*)d_in[11];
    const float* a_lo     = (const float*)d_in[12];
    const float* u_eps    = (const float*)d_in[13];
    const int*   src      = (const int*)d_in[14];
    const int*   dst      = (const int*)d_in[15];
    const int*   idx_src_hi = (const int*)d_in[16];
    const int*   idx_src_lo = (const int*)d_in[17];
    const int*   idx_dst_hi = (const int*)d_in[18];
    const int*   idx_dst_lo = (const int*)d_in[19];
    float* out = (float*)d_out;

    k_imp<<<1, 32>>>(b_hi, a_hi, b_lo, a_lo);
    dim3 gfold(64, 4);
    k_fold<<<gfold, 256>>>(w1_src, w1_dst);
    k_gemm<<<2 * NB_BR, 256>>>(node_emb, b1_src, b1_dst, w2_src, w2_dst,
                               b2_src, b2_dst,
                               idx_src_lo, idx_src_hi, idx_dst_lo, idx_dst_hi);
    k_edge<<<NPART, 256>>>(src, dst, u_eps, out);
}

// round 11
// speedup vs baseline: 6.0617x; 1.6315x over previous
#include <cuda_runtime.h>
#include <cuda_bf16.h>
#include <math.h>
#include <cstdint>

#define Nn 50000
#define Ee 1600000
#define NLO 40000
#define NHI 10000

// ---------------------------------------------------------------------------
// Scratch (static device arrays)
// ---------------------------------------------------------------------------
__device__ float g_h[2][256];           // impulse responses lo/hi
// Folded W1, split bf16, packed per 16-k segment as LDS.128-ready quads:
// word index within combo = ksg*1024 + nt*128 + lane*4 + slot
// slot: 0=h0(r=0) 1=h1(r=1) 2=l0 3=l1 ; bf16 halfword p = kr&1
__device__ uint32_t g_wtf[4][16384];
__device__ float g_wsrc[Nn];
__device__ float g_wdst[Nn];
__device__ double g_part[2048];
__device__ unsigned g_cnt = 0;

// ---------------------------------------------------------------------------
// cp.async helpers
// ---------------------------------------------------------------------------
__device__ __forceinline__ void cpa16(void* dst_smem, const void* src_gmem) {
    unsigned d = (unsigned)__cvta_generic_to_shared(dst_smem);
    asm volatile("cp.async.cg.shared.global [%0], [%1], 16;" :: "r"(d), "l"(src_gmem));
}
__device__ __forceinline__ void cpa_commit() { asm volatile("cp.async.commit_group;"); }
template<int NW> __device__ __forceinline__ void cpa_wait() {
    asm volatile("cp.async.wait_group %0;" :: "n"(NW));
}

// ---------------------------------------------------------------------------
// bf16 mma.sync m16n8k16
// ---------------------------------------------------------------------------
__device__ __forceinline__ void mma16816(float* c, const uint32_t* a,
                                         uint32_t b0, uint32_t b1) {
    asm volatile(
        "mma.sync.aligned.m16n8k16.row.col.f32.bf16.bf16.f32 "
        "{%0,%1,%2,%3}, {%4,%5,%6,%7}, {%8,%9}, {%0,%1,%2,%3};"
        : "+f"(c[0]), "+f"(c[1]), "+f"(c[2]), "+f"(c[3])
        : "r"(a[0]), "r"(a[1]), "r"(a[2]), "r"(a[3]), "r"(b0), "r"(b1));
}

// ---------------------------------------------------------------------------
// K0: impulse responses
// ---------------------------------------------------------------------------
__global__ void k_imp(const float* __restrict__ bhi, const float* __restrict__ ahi,
                      const float* __restrict__ blo, const float* __restrict__ alo)
{
    int f = threadIdx.x;
    if (f >= 2) return;
    const float* bc = f ? bhi : blo;
    const float* ac = f ? ahi : alo;
    float inv = 1.0f / ac[0];
    float b0 = bc[0]*inv, b1 = bc[1]*inv, b2 = bc[2]*inv,
          b3 = bc[3]*inv, b4 = bc[4]*inv, b5 = bc[5]*inv;
    float a1 = ac[1]*inv, a2 = ac[2]*inv, a3 = ac[3]*inv,
          a4 = ac[4]*inv, a5 = ac[5]*inv;
    float z0=0.f, z1=0.f, z2=0.f, z3=0.f, z4=0.f;
    for (int d = 0; d < 256; d++) {
        float xv = (d == 0) ? 1.0f : 0.0f;
        float y  = fmaf(b0, xv, z0);
        z0 = fmaf(-a1, y, fmaf(b1, xv, z1));
        z1 = fmaf(-a2, y, fmaf(b2, xv, z2));
        z2 = fmaf(-a3, y, fmaf(b3, xv, z3));
        z3 = fmaf(-a4, y, fmaf(b4, xv, z4));
        z4 = fmaf(-a5, y, b5 * xv);
        g_h[f][d] = y;
    }
}

// ---------------------------------------------------------------------------
// K1: fold IIR into W1, split bf16, packed in LDS.128-ready fragment quads.
//   wt(combo,k,n) = sum_{d>=k} h_f[d-k] * W1_br[d][n]
// grid (64, 4 combos), block 256: k = bx*4 + t/64, n = t%64
// ---------------------------------------------------------------------------
__global__ void __launch_bounds__(256) k_fold(
    const float* __restrict__ w1s, const float* __restrict__ w1d)
{
    __shared__ float hs[256];
    int combo = blockIdx.y;
    int f  = combo & 1;
    int br = combo >> 1;
    int t  = threadIdx.x;
    int k  = blockIdx.x * 4 + (t >> 6);
    int n  = t & 63;
    for (int d = t; d < 256; d += 256) hs[d] = g_h[f][d];
    __syncthreads();

    const float* W1 = br ? w1d : w1s;
    float acc = 0.f;
    for (int d = k; d < 256; d++)
        acc = fmaf(hs[d - k], __ldg(W1 + d*64 + n), acc);

    __nv_bfloat16 hi = __float2bfloat16(acc);
    __nv_bfloat16 lo = __float2bfloat16(acc - __bfloat162float(hi));

    int ks = k >> 4, kr = k & 15;
    int r  = kr >> 3, p = kr & 1;
    int lane = (n & 7) * 4 + ((kr & 7) >> 1);
    int nt = n >> 3;
    uint32_t base32 = (uint32_t)(ks*1024 + nt*128 + lane*4);
    __nv_bfloat16* w = (__nv_bfloat16*)(g_wtf[combo] + base32);
    w[r*2 + p]       = hi;   // slot r   (h0/h1)
    w[(2+r)*2 + p]   = lo;   // slot 2+r (l0/l1)
}

// ---------------------------------------------------------------------------
// K2: gathered split-bf16 HMMA GEMM + fused relu/w2 epilogue.
// 256 threads / 8 warps; tile 128 gathered rows x 64 cols; K=256, KC=16,
// 3-stage cp.async ring for BOTH the A gather and the W fragments.
// Warp w: rows [16w,16w+16), all 8 n-tiles. Per chunk: 4 LDS.64 (A) +
// 8 LDS.128 (W) + 24 HMMA.
// ---------------------------------------------------------------------------
#define NB_LO 313
#define NB_HI 79
#define NB_BR 392
#define KC 16
#define NCH 16
#define A_LD 20   // 80B row stride, 16B-aligned

__global__ void __launch_bounds__(256) k_gemm(
    const float* __restrict__ x,
    const float* __restrict__ b1s, const float* __restrict__ b1d,
    const float* __restrict__ w2s, const float* __restrict__ w2d,
    const float* __restrict__ b2s, const float* __restrict__ b2d,
    const int* __restrict__ isl, const int* __restrict__ ish,
    const int* __restrict__ idl, const int* __restrict__ idh)
{
    __shared__ float As[3][128 * A_LD];     // 30720 B
    __shared__ uint32_t Wsm[3][1024];       // 12288 B
    __shared__ int nids[128];

    int t = threadIdx.x;
    int warp = t >> 5, lane = t & 31;

    int bx = blockIdx.x;
    int br = bx / NB_BR;
    int r  = bx - br * NB_BR;
    int f, pos0, lim;
    if (r < NB_LO) { f = 0; pos0 = r * 128;            lim = NLO; }
    else           { f = 1; pos0 = (r - NB_LO) * 128;  lim = NHI; }
    int combo = br * 2 + f;
    const int* idx = f ? (br ? idh : ish) : (br ? idl : isl);
    const uint32_t* wsrc = g_wtf[combo];

    if (t < 128) {
        int p = pos0 + t;
        nids[t] = (p < lim) ? __ldg(idx + p) : 0;
    }
    __syncthreads();

    float acc[8][4];
#pragma unroll
    for (int nt = 0; nt < 8; nt++)
#pragma unroll
        for (int q = 0; q < 4; q++) acc[nt][q] = 0.f;

    // A: 128 rows x 16 floats = 512 float4s (2/thread); W: 1024 words (1 cpa16/thread)
#define STAGE(c) do { int _b = (c) % 3; int _kc = (c) * KC;                   \
        _Pragma("unroll")                                                     \
        for (int q = 0; q < 2; q++) {                                         \
            int u = t + 256*q; int row = u >> 2, seg = u & 3;                 \
            cpa16(&As[_b][row * A_LD + seg * 4],                              \
                  x + (size_t)nids[row] * 256 + _kc + seg * 4);               \
        }                                                                     \
        cpa16(&Wsm[_b][t * 4], wsrc + (c) * 1024 + t * 4);                    \
        cpa_commit(); } while (0)

    STAGE(0);
    STAGE(1);

#pragma unroll 1
    for (int c = 0; c < NCH; c++) {
        if (c + 2 < NCH)      { STAGE(c + 2); cpa_wait<2>(); }
        else if (c + 1 < NCH) { cpa_wait<1>(); }
        else                  { cpa_wait<0>(); }
        __syncthreads();

        int buf = c % 3;
        const float* Ab = &As[buf][(warp * 16) * A_LD];
        int rrow = lane >> 2;           // 0..7
        int kp   = (lane & 3) * 2;      // 0,2,4,6

        float2 f0 = *(const float2*)(Ab + rrow * A_LD + kp);
        float2 f1 = *(const float2*)(Ab + (rrow + 8) * A_LD + kp);
        float2 f2 = *(const float2*)(Ab + rrow * A_LD + kp + 8);
        float2 f3 = *(const float2*)(Ab + (rrow + 8) * A_LD + kp + 8);

        uint32_t ahi[4], alo[4];
        float2 fs[4] = {f0, f1, f2, f3};
#pragma unroll
        for (int i = 0; i < 4; i++) {
            __nv_bfloat162 hp;
            hp.x = __float2bfloat16(fs[i].x);
            hp.y = __float2bfloat16(fs[i].y);
            __nv_bfloat162 lp;
            lp.x = __float2bfloat16(fs[i].x - __bfloat162float(hp.x));
            lp.y = __float2bfloat16(fs[i].y - __bfloat162float(hp.y));
            ahi[i] = *(uint32_t*)&hp;
            alo[i] = *(uint32_t*)&lp;
        }

        const uint4* Wb = (const uint4*)Wsm[buf] + lane;
#pragma unroll
        for (int nt = 0; nt < 8; nt++) {
            uint4 wv = Wb[nt * 32];     // {h0, h1, l0, l1}
            mma16816(acc[nt], ahi, wv.x, wv.y);
            mma16816(acc[nt], ahi, wv.z, wv.w);
            mma16816(acc[nt], alo, wv.x, wv.y);
        }
        __syncthreads();
    }
#undef STAGE

    // epilogue: relu(h + b1) . w2 ; thread covers rows rA, rA+8, 2 cols/nt
    const float* b1p = br ? b1d : b1s;
    const float* w2p = br ? w2d : w2s;
    float pA = 0.f, pB = 0.f;
#pragma unroll
    for (int nt = 0; nt < 8; nt++) {
        int n0 = nt * 8 + (lane & 3) * 2;
        float ba = __ldg(b1p + n0),     bb = __ldg(b1p + n0 + 1);
        float wa = __ldg(w2p + n0),     wb = __ldg(w2p + n0 + 1);
        pA += fmaxf(acc[nt][0] + ba, 0.f) * wa + fmaxf(acc[nt][1] + bb, 0.f) * wb;
        pB += fmaxf(acc[nt][2] + ba, 0.f) * wa + fmaxf(acc[nt][3] + bb, 0.f) * wb;
    }
    pA += __shfl_xor_sync(0xffffffffu, pA, 1);
    pA += __shfl_xor_sync(0xffffffffu, pA, 2);
    pB += __shfl_xor_sync(0xffffffffu, pB, 1);
    pB += __shfl_xor_sync(0xffffffffu, pB, 2);
    if ((lane & 3) == 0) {
        float b2v = __ldg(br ? b2d : b2s);
        float* outw = br ? g_wdst : g_wsrc;
        int base = f ? NLO : 0;
        int rowA = pos0 + warp * 16 + (lane >> 2);
        if (rowA < lim)     outw[base + rowA]     = pA + b2v;
        if (rowA + 8 < lim) outw[base + rowA + 8] = pB + b2v;
    }
}

// ---------------------------------------------------------------------------
// K3: edge gate, 16 edges/thread (4 independent quads), log-free sigmoid,
// fused deterministic reduction.
// sigmoid((logit(eps)+w)/0.5) = 1 / (1 + ((1-eps)/eps)^2 * exp(-2w))
// ---------------------------------------------------------------------------
#define EDGES_PER_BLOCK 4096
#define NPART 391   // 391*4096 >= 1.6M

__device__ __forceinline__ double edge_quad(
    const int* __restrict__ src, const int* __restrict__ dst,
    const float* __restrict__ u, float* __restrict__ out, int base)
{
    int4   s4 = *(const int4*)(src + base);
    int4   d4 = *(const int4*)(dst + base);
    float4 u4 = *(const float4*)(u + base);
    float wv[4] = { __ldg(&g_wsrc[s4.x]) + __ldg(&g_wdst[d4.x]),
                    __ldg(&g_wsrc[s4.y]) + __ldg(&g_wdst[d4.y]),
                    __ldg(&g_wsrc[s4.z]) + __ldg(&g_wdst[d4.z]),
                    __ldg(&g_wsrc[s4.w]) + __ldg(&g_wdst[d4.w]) };
    float uu[4] = { u4.x, u4.y, u4.z, u4.w };
    double local = 0.0;
#pragma unroll
    for (int q = 0; q < 4; q++) {
        float eps  = 0.9999f - 0.9998f * uu[q];
        float onem = 0.0001f + 0.9998f * uu[q];
        float rr   = __fdividef(onem, eps);
        float ge   = __expf(-2.0f * wv[q]);
        float aug  = __fdividef(1.0f, fmaf(rr * rr, ge, 1.0f));
        out[1 + base + q] = aug;
        local += (double)aug;
    }
    return local;
}

__global__ void __launch_bounds__(256) k_edge(
    const int* __restrict__ src, const int* __restrict__ dst,
    const float* __restrict__ u, float* __restrict__ out)
{
    __shared__ double red[256];
    __shared__ int isLast;
    int t = threadIdx.x;
    int blk0 = blockIdx.x * EDGES_PER_BLOCK;
    double local = 0.0;
#pragma unroll
    for (int qq = 0; qq < 4; qq++) {
        int b = blk0 + qq * 1024 + t * 4;
        if (b < Ee) local += edge_quad(src, dst, u, out, b);
    }

    red[t] = local;
    __syncthreads();
    for (int off = 128; off; off >>= 1) {
        if (t < off) red[t] += red[t + off];
        __syncthreads();
    }
    if (t == 0) {
        g_part[blockIdx.x] = red[0];
        __threadfence();
        unsigned old = atomicAdd(&g_cnt, 1u);
        isLast = (old == NPART - 1);
    }
    __syncthreads();
    if (isLast) {
        double l2 = 0.0;
        for (int i = t; i < NPART; i += 256) l2 += g_part[i];
        red[t] = l2;
        __syncthreads();
        for (int off = 128; off; off >>= 1) {
            if (t < off) red[t] += red[t + off];
            __syncthreads();
        }
        if (t == 0) {
            out[0] = (float)(1.0 - red[0] / (double)Ee);
            g_cnt = 0;
        }
    }
}

// ---------------------------------------------------------------------------
extern "C" void kernel_launch(void* const* d_in, const int* in_sizes, int n_in,
                              void* d_out, int out_size)
{
    const float* node_emb = (const float*)d_in[0];
    const float* w1_src   = (const float*)d_in[1];
    const float* b1_src   = (const float*)d_in[2];
    const float* w2_src   = (const float*)d_in[3];
    const float* b2_src   = (const float*)d_in[4];
    const float* w1_dst   = (const float*)d_in[5];
    const float* b1_dst   = (const float*)d_in[6];
    const float* w2_dst   = (const float*)d_in[7];
    const float* b2_dst   = (const float*)d_in[8];
    const float* b_hi     = (const float*)d_in[9];
    const float* a_hi     = (const float*)d_in[10];
    const float* b_lo     = (const float*)d_in[11];
    const float* a_lo     = (const float*)d_in[12];
    const float* u_eps    = (const float*)d_in[13];
    const int*   src      = (const int*)d_in[14];
    const int*   dst      = (const int*)d_in[15];
    const int*   idx_src_hi = (const int*)d_in[16];
    const int*   idx_src_lo = (const int*)d_in[17];
    const int*   idx_dst_hi = (const int*)d_in[18];
    const int*   idx_dst_lo = (const int*)d_in[19];
    float* out = (float*)d_out;

    k_imp<<<1, 32>>>(b_hi, a_hi, b_lo, a_lo);
    dim3 gfold(64, 4);
    k_fold<<<gfold, 256>>>(w1_src, w1_dst);
    k_gemm<<<2 * NB_BR, 256>>>(node_emb, b1_src, b1_dst, w2_src, w2_dst,
                               b2_src, b2_dst,
                               idx_src_lo, idx_src_hi, idx_dst_lo, idx_dst_hi);
    k_edge<<<NPART, 256>>>(src, dst, u_eps, out);
}